// round 11
// baseline (speedup 1.0000x reference)
#include <cuda_runtime.h>
#include <math.h>
#include <stdint.h>

// Problem constants
#define NB   2
#define TT   1024
#define DD   1024
#define HH   16
#define DHH  64
#define WW   64
#define WIN  129

// GEMM dims
#define GM 2048
#define GN 1024
#define GK 1024
// Tiling
#define BM 128
#define BN 128
#define BK 32
#define SROW 40                 // stride mod 32 = 8 -> conflict-free LDS.64/STS.128
#define NITER (GK / BK)
#define SMEM_FLOATS (2 * 2 * BM * SROW)
#define SMEM_BYTES  (SMEM_FLOATS * 4)        // 81920

// Attention tiling: CTA = 32 t-rows, window union 160
#define AR   32
#define AU   160
#define AQS  66
#define AKS  66
#define AVS  68
#define APS  164
#define SM_Q   0
#define SM_K   2112
#define SM_V   12672
#define SM_RED 23552          // [32][33]
#define SM_MAX 24608
#define SM_INV 24640
#define ATT_SMEM_BYTES (24672 * 4)   // 98688

// Scratch (device globals: allocation-free per harness rules)
__device__ float g_q[NB * TT * DD];
__device__ float g_k[NB * TT * DD];
__device__ float g_v[NB * TT * DD];
__device__ float g_attn[NB * TT * DD];

__device__ __forceinline__ float to_tf32(float x) {
    float r;
    asm("cvt.rna.tf32.f32 %0, %1;" : "=f"(r) : "f"(x));
    return r;
}

__device__ __forceinline__ void mma_16x8x8_tf32(float* d, const uint32_t* a,
                                                const uint32_t* b) {
    asm volatile(
        "mma.sync.aligned.m16n8k8.row.col.f32.tf32.tf32.f32 "
        "{%0,%1,%2,%3}, {%4,%5,%6,%7}, {%8,%9}, {%0,%1,%2,%3};"
        : "+f"(d[0]), "+f"(d[1]), "+f"(d[2]), "+f"(d[3])
        : "r"(a[0]), "r"(a[1]), "r"(a[2]), "r"(a[3]),
          "r"(b[0]), "r"(b[1]));
}

// ---------------------------------------------------------------------------
// tf32 mma.sync GEMM: C[M,N] = A[M,K] @ B[N,K]^T + bias
// Register-staged double buffer (R6 structure). Fragment loads are LDS.64 via
// the K-permutation trick: fragment col c <- phys col 2c, c+4 <- phys 2c+1,
// applied identically to A and B (reduction order is permutation-invariant).
// ---------------------------------------------------------------------------
__device__ __forceinline__ void gemm_tc_body(
    const float* __restrict__ A, const float* __restrict__ B,
    const float* __restrict__ bias, float* __restrict__ C)
{
    extern __shared__ float smem[];
    float* Asm = smem;
    float* Bsm = smem + 2 * BM * SROW;

    const int tid  = threadIdx.x;
    const int lane = tid & 31;
    const int wid  = tid >> 5;
    const int wm   = wid >> 2;
    const int wn   = wid & 3;
    const int row0 = blockIdx.y * BM;
    const int col0 = blockIdx.x * BN;

    const int lrow = tid >> 3;
    const int lq   = tid & 7;

    float acc[4][4][4];
#pragma unroll
    for (int m = 0; m < 4; ++m)
#pragma unroll
        for (int n = 0; n < 4; ++n)
#pragma unroll
            for (int e = 0; e < 4; ++e) acc[m][n][e] = 0.f;

    float4 pa[4], pb[4];

#pragma unroll
    for (int p = 0; p < 4; ++p) {
        int r = p * 32 + lrow;
        pa[p] = *(const float4*)(A + (size_t)(row0 + r) * GK + lq * 4);
        pb[p] = *(const float4*)(B + (size_t)(col0 + r) * GK + lq * 4);
    }
#pragma unroll
    for (int p = 0; p < 4; ++p) {
        int r = p * 32 + lrow;
        float4 va = pa[p], vb = pb[p];
        va.x = to_tf32(va.x); va.y = to_tf32(va.y);
        va.z = to_tf32(va.z); va.w = to_tf32(va.w);
        vb.x = to_tf32(vb.x); vb.y = to_tf32(vb.y);
        vb.z = to_tf32(vb.z); vb.w = to_tf32(vb.w);
        *(float4*)(Asm + r * SROW + lq * 4) = va;
        *(float4*)(Bsm + r * SROW + lq * 4) = vb;
    }
    __syncthreads();

    const int c  = lane & 3;
    const int r4 = lane >> 2;

    for (int i = 0; i < NITER; ++i) {
        const int buf = i & 1;
        const float* Ab = Asm + buf * (BM * SROW);
        const float* Bb = Bsm + buf * (BM * SROW);

        if (i + 1 < NITER) {
            const int k0 = (i + 1) * BK;
#pragma unroll
            for (int p = 0; p < 4; ++p) {
                int r = p * 32 + lrow;
                pa[p] = *(const float4*)(A + (size_t)(row0 + r) * GK + k0 + lq * 4);
                pb[p] = *(const float4*)(B + (size_t)(col0 + r) * GK + k0 + lq * 4);
            }
        }

        // LDS.64 fragment bases: each thread reads contiguous (2c, 2c+1) pairs
        const float* Au = Ab + (wm * 64 + r4) * SROW + 2 * c;
        const float* Bu = Bb + (wn * 32 + r4) * SROW + 2 * c;

#pragma unroll
        for (int kk = 0; kk < 4; ++kk) {
            const int ko = kk * 8;
            uint32_t af[4][4], bf[4][2];
#pragma unroll
            for (int m = 0; m < 4; ++m) {
                uint2 lo = *(const uint2*)(Au + (m * 16 + 0) * SROW + ko);
                uint2 hi = *(const uint2*)(Au + (m * 16 + 8) * SROW + ko);
                af[m][0] = lo.x;  // frag col c      <- phys 2c
                af[m][2] = lo.y;  // frag col c+4    <- phys 2c+1
                af[m][1] = hi.x;
                af[m][3] = hi.y;
            }
#pragma unroll
            for (int n = 0; n < 4; ++n) {
                uint2 bb = *(const uint2*)(Bu + (n * 8) * SROW + ko);
                bf[n][0] = bb.x;  // frag col c   <- phys 2c
                bf[n][1] = bb.y;  // frag col c+4 <- phys 2c+1
            }
#pragma unroll
            for (int m = 0; m < 4; ++m)
#pragma unroll
                for (int n = 0; n < 4; ++n)
                    mma_16x8x8_tf32(acc[m][n], af[m], bf[n]);
        }

        if (i + 1 < NITER) {
            float* Aw = Asm + (buf ^ 1) * (BM * SROW);
            float* Bw = Bsm + (buf ^ 1) * (BM * SROW);
#pragma unroll
            for (int p = 0; p < 4; ++p) {
                int r = p * 32 + lrow;
                float4 va = pa[p], vb = pb[p];
                va.x = to_tf32(va.x); va.y = to_tf32(va.y);
                va.z = to_tf32(va.z); va.w = to_tf32(va.w);
                vb.x = to_tf32(vb.x); vb.y = to_tf32(vb.y);
                vb.z = to_tf32(vb.z); vb.w = to_tf32(vb.w);
                *(float4*)(Aw + r * SROW + lq * 4) = va;
                *(float4*)(Bw + r * SROW + lq * 4) = vb;
            }
            __syncthreads();
        }
    }

    // Epilogue: D fragment layout is unaffected by the K permutation.
#pragma unroll
    for (int m = 0; m < 4; ++m) {
#pragma unroll
        for (int h = 0; h < 2; ++h) {
            const int grow = row0 + wm * 64 + m * 16 + r4 + 8 * h;
            float* crow = C + (size_t)grow * GN;
#pragma unroll
            for (int n = 0; n < 4; ++n) {
                const int gcol = col0 + wn * 32 + n * 8 + 2 * c;
                float2 o;
                o.x = acc[m][n][2 * h + 0] + __ldg(&bias[gcol + 0]);
                o.y = acc[m][n][2 * h + 1] + __ldg(&bias[gcol + 1]);
                *(float2*)(crow + gcol) = o;
            }
        }
    }
}

__global__ __launch_bounds__(256, 2) void gemm_qkv_tc(
    const float* __restrict__ x,
    const float* __restrict__ wq, const float* __restrict__ bq,
    const float* __restrict__ wk, const float* __restrict__ bk,
    const float* __restrict__ wv, const float* __restrict__ bv)
{
    const float* B; const float* bias; float* C;
    if (blockIdx.z == 0)      { B = wq; bias = bq; C = g_q; }
    else if (blockIdx.z == 1) { B = wk; bias = bk; C = g_k; }
    else                      { B = wv; bias = bv; C = g_v; }
    gemm_tc_body(x, B, bias, C);
}

__global__ __launch_bounds__(256, 2) void gemm_out_tc(
    const float* __restrict__ wo, const float* __restrict__ bo,
    float* __restrict__ out)
{
    gemm_tc_body(g_attn, wo, bo, out);
}

// ---------------------------------------------------------------------------
// Tiled windowed attention (fp32). CTA = 32 t-rows; union 160 positions.
// (unchanged from R10 — verified)
// ---------------------------------------------------------------------------
__global__ __launch_bounds__(256) void attn_tile_kernel()
{
    extern __shared__ float sm[];
    float* Qs   = sm + SM_Q;
    float* Ks   = sm + SM_K;
    float* Vs   = sm + SM_V;
    float* red  = sm + SM_RED;
    float* rmax = sm + SM_MAX;
    float* rinv = sm + SM_INV;

    const int tid = threadIdx.x;
    const int t0  = blockIdx.x * AR;
    const int nh  = blockIdx.y;
    const int h   = nh & (HH - 1);
    const int n   = nh >> 4;
    const size_t base = (size_t)n * TT * DD + (size_t)h * DHH;

    // ---- loads ----
    for (int idx = tid; idx < AR * 16; idx += 256) {
        int r = idx >> 4, cc = (idx & 15) << 2;
        float4 v = *(const float4*)(g_q + base + (size_t)(t0 + r) * DD + cc);
        float* dst = Qs + r * AQS + cc;
        ((float2*)dst)[0] = make_float2(v.x * 0.125f, v.y * 0.125f);
        ((float2*)dst)[1] = make_float2(v.z * 0.125f, v.w * 0.125f);
    }
    for (int idx = tid; idx < AU * 16; idx += 256) {
        int r = idx >> 4, cc = (idx & 15) << 2;
        int pos = min(max(t0 - 64 + r, 0), TT - 1);
        float4 kv = *(const float4*)(g_k + base + (size_t)pos * DD + cc);
        float* kd = Ks + r * AKS + cc;
        ((float2*)kd)[0] = make_float2(kv.x, kv.y);
        ((float2*)kd)[1] = make_float2(kv.z, kv.w);
        float4 vv = *(const float4*)(g_v + base + (size_t)pos * DD + cc);
        *(float4*)(Vs + r * AVS + cc) = vv;
    }
    __syncthreads();

    const int lane = tid & 31, wid = tid >> 5;
    const int lm = lane >> 2, ln = lane & 3;     // lanes 8(M) x 4(N)
    const int colb = wid * 20 + ln * 5;          // 5 cols per thread

    // ---- phase 1: S = Q @ K^T ----
    float acc[4][5];
#pragma unroll
    for (int i = 0; i < 4; ++i)
#pragma unroll
        for (int j = 0; j < 5; ++j) acc[i][j] = 0.f;

    const float* Qp = Qs + (lm * 4) * AQS;
    const float* Kp = Ks + colb * AKS;
    for (int k2 = 0; k2 < 32; ++k2) {
        float2 a[4], b[5];
#pragma unroll
        for (int i = 0; i < 4; ++i)
            a[i] = *(const float2*)(Qp + i * AQS + 2 * k2);
#pragma unroll
        for (int j = 0; j < 5; ++j)
            b[j] = *(const float2*)(Kp + j * AKS + 2 * k2);
#pragma unroll
        for (int i = 0; i < 4; ++i)
#pragma unroll
            for (int j = 0; j < 5; ++j)
                acc[i][j] += a[i].x * b[j].x + a[i].y * b[j].y;
    }

    // ---- phase 2: mask + 2-pass softmax ----
    const int lob = 64 - t0;
    const int hib = 1087 - t0;
#pragma unroll
    for (int i = 0; i < 4; ++i) {
        int row = lm * 4 + i;
        int lo = max(row, lob), hi = min(row + 128, hib);
        float m = -1e30f;
#pragma unroll
        for (int j = 0; j < 5; ++j) {
            int cc = colb + j;
            if (cc < lo || cc > hi) acc[i][j] = -1e30f;
            m = fmaxf(m, acc[i][j]);
        }
        red[row * 33 + wid * 4 + ln] = m;
    }
    __syncthreads();
    if (tid < AR) {
        float m = red[tid * 33];
#pragma unroll
        for (int p = 1; p < 32; ++p) m = fmaxf(m, red[tid * 33 + p]);
        rmax[tid] = m;
    }
    __syncthreads();

    float* Ps = Ks;
#pragma unroll
    for (int i = 0; i < 4; ++i) {
        int row = lm * 4 + i;
        float m = rmax[row];
        float s = 0.f;
        float* pd = Ps + row * APS + colb;
#pragma unroll
        for (int j = 0; j < 5; ++j) {
            float e = __expf(acc[i][j] - m);
            s += e;
            pd[j] = e;
        }
        red[row * 33 + wid * 4 + ln] = s;
    }
    __syncthreads();
    if (tid < AR) {
        float s = 0.f;
#pragma unroll
        for (int p = 0; p < 32; ++p) s += red[tid * 33 + p];
        rinv[tid] = 1.0f / s;
    }
    __syncthreads();

    // ---- phase 3: out = P @ V  (2 rows x 4 dh per thread) ----
    const int dhg  = tid & 15;
    const int rowg = tid >> 4;
    const int pcol = dhg * 4;
    const int r0p  = rowg * 2;

    float pv0[4] = {0.f, 0.f, 0.f, 0.f};
    float pv1[4] = {0.f, 0.f, 0.f, 0.f};

    const float* P0 = Ps + (r0p + 0) * APS;
    const float* P1 = Ps + (r0p + 1) * APS;
    const float* Vp = Vs + pcol;

#pragma unroll 2
    for (int k = 0; k < AU; k += 2) {
        float2 p0 = *(const float2*)(P0 + k);
        float2 p1 = *(const float2*)(P1 + k);
        float4 v0 = *(const float4*)(Vp + (k + 0) * AVS);
        float4 v1 = *(const float4*)(Vp + (k + 1) * AVS);
        pv0[0] += p0.x * v0.x + p0.y * v1.x;
        pv0[1] += p0.x * v0.y + p0.y * v1.y;
        pv0[2] += p0.x * v0.z + p0.y * v1.z;
        pv0[3] += p0.x * v0.w + p0.y * v1.w;
        pv1[0] += p1.x * v0.x + p1.y * v1.x;
        pv1[1] += p1.x * v0.y + p1.y * v1.y;
        pv1[2] += p1.x * v0.z + p1.y * v1.z;
        pv1[3] += p1.x * v0.w + p1.y * v1.w;
    }

    const float i0 = rinv[r0p + 0];
    const float i1 = rinv[r0p + 1];
    float* o0 = g_attn + base + (size_t)(t0 + r0p + 0) * DD + pcol;
    float* o1 = g_attn + base + (size_t)(t0 + r0p + 1) * DD + pcol;
    *(float4*)o0 = make_float4(pv0[0] * i0, pv0[1] * i0, pv0[2] * i0, pv0[3] * i0);
    *(float4*)o1 = make_float4(pv1[0] * i1, pv1[1] * i1, pv1[2] * i1, pv1[3] * i1);
}

// ---------------- launch ----------------
extern "C" void kernel_launch(void* const* d_in, const int* in_sizes, int n_in,
                              void* d_out, int out_size)
{
    const float* x  = (const float*)d_in[0];
    const float* wq = (const float*)d_in[1];
    const float* bq = (const float*)d_in[2];
    const float* wk = (const float*)d_in[3];
    const float* bk = (const float*)d_in[4];
    const float* wv = (const float*)d_in[5];
    const float* bv = (const float*)d_in[6];
    const float* wo = (const float*)d_in[7];
    const float* bo = (const float*)d_in[8];

    cudaFuncSetAttribute(gemm_qkv_tc,
                         cudaFuncAttributeMaxDynamicSharedMemorySize, SMEM_BYTES);
    cudaFuncSetAttribute(gemm_out_tc,
                         cudaFuncAttributeMaxDynamicSharedMemorySize, SMEM_BYTES);
    cudaFuncSetAttribute(attn_tile_kernel,
                         cudaFuncAttributeMaxDynamicSharedMemorySize, ATT_SMEM_BYTES);

    dim3 gq(GN / BN, GM / BM, 3);
    gemm_qkv_tc<<<gq, 256, SMEM_BYTES>>>(x, wq, bq, wk, bk, wv, bv);

    attn_tile_kernel<<<dim3(TT / AR, NB * HH), 256, ATT_SMEM_BYTES>>>();

    dim3 go(GN / BN, GM / BM);
    gemm_out_tc<<<go, 256, SMEM_BYTES>>>(wo, bo, (float*)d_out);
}

// round 12
// speedup vs baseline: 1.1406x; 1.1406x over previous
#include <cuda_runtime.h>
#include <math.h>
#include <stdint.h>

// Problem constants
#define NB   2
#define TT   1024
#define DD   1024
#define HH   16
#define DHH  64
#define WW   64
#define WIN  129

// GEMM dims
#define GM 2048
#define GN 1024
#define GK 1024
// Tiling (R10 verified: 110.8us QKV)
#define BM 128
#define BN 128
#define BK 32
#define SROW 36
#define NITER (GK / BK)
#define SMEM_FLOATS (2 * 2 * BM * SROW)
#define SMEM_BYTES  (SMEM_FLOATS * 4)        // 73728

// Attention tiling: CTA = 32 t-rows, window union 160
#define AR   32
#define AU   160
#define AQS  68                  // 4*r4+c covers 32 banks -> conflict-free frags
#define AKS  68
#define AVS  68
#define APS  164
#define SM_Q   0                 // Q[32][68]   = 2176
#define SM_K   2176              // K[160][68]  = 10880 (reused as P[32][164])
#define SM_V   13056             // V[160][68]  = 10880
#define SM_RED 23936             // red[32][5]  = 160
#define SM_INV 24096             // rinv[32]
#define ATT_SMEM_BYTES (24128 * 4)   // 96512

// Scratch (device globals: allocation-free per harness rules)
__device__ float g_q[NB * TT * DD];
__device__ float g_k[NB * TT * DD];
__device__ float g_v[NB * TT * DD];
__device__ float g_attn[NB * TT * DD];

__device__ __forceinline__ float to_tf32(float x) {
    float r;
    asm("cvt.rna.tf32.f32 %0, %1;" : "=f"(r) : "f"(x));
    return r;
}

__device__ __forceinline__ void mma_16x8x8_tf32(float* d, const uint32_t* a,
                                                const uint32_t* b) {
    asm volatile(
        "mma.sync.aligned.m16n8k8.row.col.f32.tf32.tf32.f32 "
        "{%0,%1,%2,%3}, {%4,%5,%6,%7}, {%8,%9}, {%0,%1,%2,%3};"
        : "+f"(d[0]), "+f"(d[1]), "+f"(d[2]), "+f"(d[3])
        : "r"(a[0]), "r"(a[1]), "r"(a[2]), "r"(a[3]),
          "r"(b[0]), "r"(b[1]));
}

// ---------------------------------------------------------------------------
// tf32 mma.sync GEMM (R10 verbatim: register-staged double buffer, LDS.32
// fragments, SROW=36; measured 110.8us on QKV)
// ---------------------------------------------------------------------------
__device__ __forceinline__ void gemm_tc_body(
    const float* __restrict__ A, const float* __restrict__ B,
    const float* __restrict__ bias, float* __restrict__ C)
{
    extern __shared__ float smem[];
    float* Asm = smem;
    float* Bsm = smem + 2 * BM * SROW;

    const int tid  = threadIdx.x;
    const int lane = tid & 31;
    const int wid  = tid >> 5;
    const int wm   = wid >> 2;
    const int wn   = wid & 3;
    const int row0 = blockIdx.y * BM;
    const int col0 = blockIdx.x * BN;

    const int lrow = tid >> 3;
    const int lq   = tid & 7;

    float acc[4][4][4];
#pragma unroll
    for (int m = 0; m < 4; ++m)
#pragma unroll
        for (int n = 0; n < 4; ++n)
#pragma unroll
            for (int e = 0; e < 4; ++e) acc[m][n][e] = 0.f;

    float4 pa[4], pb[4];

#pragma unroll
    for (int p = 0; p < 4; ++p) {
        int r = p * 32 + lrow;
        pa[p] = *(const float4*)(A + (size_t)(row0 + r) * GK + lq * 4);
        pb[p] = *(const float4*)(B + (size_t)(col0 + r) * GK + lq * 4);
    }
#pragma unroll
    for (int p = 0; p < 4; ++p) {
        int r = p * 32 + lrow;
        float4 va = pa[p], vb = pb[p];
        va.x = to_tf32(va.x); va.y = to_tf32(va.y);
        va.z = to_tf32(va.z); va.w = to_tf32(va.w);
        vb.x = to_tf32(vb.x); vb.y = to_tf32(vb.y);
        vb.z = to_tf32(vb.z); vb.w = to_tf32(vb.w);
        *(float4*)(Asm + r * SROW + lq * 4) = va;
        *(float4*)(Bsm + r * SROW + lq * 4) = vb;
    }
    __syncthreads();

    const int c  = lane & 3;
    const int r4 = lane >> 2;

    for (int i = 0; i < NITER; ++i) {
        const int buf = i & 1;
        const float* Ab = Asm + buf * (BM * SROW);
        const float* Bb = Bsm + buf * (BM * SROW);

        if (i + 1 < NITER) {
            const int k0 = (i + 1) * BK;
#pragma unroll
            for (int p = 0; p < 4; ++p) {
                int r = p * 32 + lrow;
                pa[p] = *(const float4*)(A + (size_t)(row0 + r) * GK + k0 + lq * 4);
                pb[p] = *(const float4*)(B + (size_t)(col0 + r) * GK + k0 + lq * 4);
            }
        }

        const uint32_t* Au = (const uint32_t*)(Ab + (wm * 64 + r4) * SROW + c);
        const uint32_t* Bu = (const uint32_t*)(Bb + (wn * 32 + r4) * SROW + c);

#pragma unroll
        for (int kk = 0; kk < 4; ++kk) {
            uint32_t af[4][4], bf[4][2];
            const int ko = kk * 8;
#pragma unroll
            for (int m = 0; m < 4; ++m) {
                af[m][0] = Au[(m * 16 + 0) * SROW + ko + 0];
                af[m][1] = Au[(m * 16 + 8) * SROW + ko + 0];
                af[m][2] = Au[(m * 16 + 0) * SROW + ko + 4];
                af[m][3] = Au[(m * 16 + 8) * SROW + ko + 4];
            }
#pragma unroll
            for (int n = 0; n < 4; ++n) {
                bf[n][0] = Bu[n * 8 * SROW + ko + 0];
                bf[n][1] = Bu[n * 8 * SROW + ko + 4];
            }
#pragma unroll
            for (int m = 0; m < 4; ++m)
#pragma unroll
                for (int n = 0; n < 4; ++n)
                    mma_16x8x8_tf32(acc[m][n], af[m], bf[n]);
        }

        if (i + 1 < NITER) {
            float* Aw = Asm + (buf ^ 1) * (BM * SROW);
            float* Bw = Bsm + (buf ^ 1) * (BM * SROW);
#pragma unroll
            for (int p = 0; p < 4; ++p) {
                int r = p * 32 + lrow;
                float4 va = pa[p], vb = pb[p];
                va.x = to_tf32(va.x); va.y = to_tf32(va.y);
                va.z = to_tf32(va.z); va.w = to_tf32(va.w);
                vb.x = to_tf32(vb.x); vb.y = to_tf32(vb.y);
                vb.z = to_tf32(vb.z); vb.w = to_tf32(vb.w);
                *(float4*)(Aw + r * SROW + lq * 4) = va;
                *(float4*)(Bw + r * SROW + lq * 4) = vb;
            }
            __syncthreads();
        }
    }

#pragma unroll
    for (int m = 0; m < 4; ++m) {
#pragma unroll
        for (int h = 0; h < 2; ++h) {
            const int grow = row0 + wm * 64 + m * 16 + r4 + 8 * h;
            float* crow = C + (size_t)grow * GN;
#pragma unroll
            for (int n = 0; n < 4; ++n) {
                const int gcol = col0 + wn * 32 + n * 8 + 2 * c;
                float2 o;
                o.x = acc[m][n][2 * h + 0] + __ldg(&bias[gcol + 0]);
                o.y = acc[m][n][2 * h + 1] + __ldg(&bias[gcol + 1]);
                *(float2*)(crow + gcol) = o;
            }
        }
    }
}

__global__ __launch_bounds__(256, 2) void gemm_qkv_tc(
    const float* __restrict__ x,
    const float* __restrict__ wq, const float* __restrict__ bq,
    const float* __restrict__ wk, const float* __restrict__ bk,
    const float* __restrict__ wv, const float* __restrict__ bv)
{
    const float* B; const float* bias; float* C;
    if (blockIdx.z == 0)      { B = wq; bias = bq; C = g_q; }
    else if (blockIdx.z == 1) { B = wk; bias = bk; C = g_k; }
    else                      { B = wv; bias = bv; C = g_v; }
    gemm_tc_body(x, B, bias, C);
}

__global__ __launch_bounds__(256, 2) void gemm_out_tc(
    const float* __restrict__ wo, const float* __restrict__ bo,
    float* __restrict__ out)
{
    gemm_tc_body(g_attn, wo, bo, out);
}

// ---------------------------------------------------------------------------
// Tiled windowed attention. CTA = 32 t-rows; union 160 positions.
// Phase 1 is now tf32 mma.sync: warps = 2(M-tile of 16) x 4(col-group of 40).
// Q/K tf32-rounded at smem store; softmax in fragment domain; phase 3 as R10.
// ---------------------------------------------------------------------------
__global__ __launch_bounds__(256) void attn_tile_kernel()
{
    extern __shared__ float sm[];
    float* Qs   = sm + SM_Q;
    float* Ks   = sm + SM_K;
    float* Vs   = sm + SM_V;
    float* red  = sm + SM_RED;    // [32][5]
    float* rinv = sm + SM_INV;    // [32]

    const int tid = threadIdx.x;
    const int t0  = blockIdx.x * AR;
    const int nh  = blockIdx.y;
    const int h   = nh & (HH - 1);
    const int n   = nh >> 4;
    const size_t base = (size_t)n * TT * DD + (size_t)h * DHH;

    // ---- loads: Q (scaled + tf32), K (tf32), V (raw) ----
    for (int idx = tid; idx < AR * 16; idx += 256) {
        int r = idx >> 4, cc = (idx & 15) << 2;
        float4 v = *(const float4*)(g_q + base + (size_t)(t0 + r) * DD + cc);
        v.x = to_tf32(v.x * 0.125f); v.y = to_tf32(v.y * 0.125f);
        v.z = to_tf32(v.z * 0.125f); v.w = to_tf32(v.w * 0.125f);
        *(float4*)(Qs + r * AQS + cc) = v;
    }
    for (int idx = tid; idx < AU * 16; idx += 256) {
        int r = idx >> 4, cc = (idx & 15) << 2;
        int pos = min(max(t0 - 64 + r, 0), TT - 1);
        float4 kv = *(const float4*)(g_k + base + (size_t)pos * DD + cc);
        kv.x = to_tf32(kv.x); kv.y = to_tf32(kv.y);
        kv.z = to_tf32(kv.z); kv.w = to_tf32(kv.w);
        *(float4*)(Ks + r * AKS + cc) = kv;
        float4 vv = *(const float4*)(g_v + base + (size_t)pos * DD + cc);
        *(float4*)(Vs + r * AVS + cc) = vv;
    }
    __syncthreads();

    const int lane = tid & 31, wid = tid >> 5;
    const int r4  = lane >> 2;
    const int cfr = lane & 3;
    const int mtile = wid & 1;          // rows mtile*16 + 0..15
    const int wg    = wid >> 1;         // cols wg*40 + 0..39 (5 n-tiles)

    // ---- phase 1: S = Q @ K^T via tf32 MMA ----
    float acc[5][4];
#pragma unroll
    for (int nt = 0; nt < 5; ++nt)
#pragma unroll
        for (int e = 0; e < 4; ++e) acc[nt][e] = 0.f;

    const uint32_t* Aq = (const uint32_t*)(Qs + (mtile * 16 + r4) * AQS + cfr);
    const uint32_t* Bk = (const uint32_t*)(Ks + (wg * 40 + r4) * AKS + cfr);
#pragma unroll
    for (int ks = 0; ks < 8; ++ks) {
        const int ko = ks * 8;
        uint32_t af[4];
        af[0] = Aq[ko];
        af[1] = Aq[8 * AQS + ko];
        af[2] = Aq[ko + 4];
        af[3] = Aq[8 * AQS + ko + 4];
#pragma unroll
        for (int nt = 0; nt < 5; ++nt) {
            uint32_t bf[2];
            bf[0] = Bk[nt * 8 * AKS + ko];
            bf[1] = Bk[nt * 8 * AKS + ko + 4];
            mma_16x8x8_tf32(acc[nt], af, bf);
        }
    }

    // ---- phase 2: mask + softmax in fragment domain ----
    // Thread holds rows row0g (elems 0,1) and row0g+8 (elems 2,3),
    // cols wg*40 + nt*8 + 2*cfr + {0,1}.
    const int lob = 64 - t0;
    const int hib = 1087 - t0;
    const int row0g = mtile * 16 + r4;
    const int lo0 = max(row0g, lob),     hi0 = min(row0g + 128, hib);
    const int lo1 = max(row0g + 8, lob), hi1 = min(row0g + 136, hib);

    float m0 = -1e30f, m1 = -1e30f;
#pragma unroll
    for (int nt = 0; nt < 5; ++nt) {
#pragma unroll
        for (int e = 0; e < 2; ++e) {
            int col = wg * 40 + nt * 8 + 2 * cfr + e;
            if (col < lo0 || col > hi0) acc[nt][e] = -1e30f;
            m0 = fmaxf(m0, acc[nt][e]);
            if (col < lo1 || col > hi1) acc[nt][2 + e] = -1e30f;
            m1 = fmaxf(m1, acc[nt][2 + e]);
        }
    }
    // reduce across the 4 lanes sharing each row (xor 1,2 toggle cfr only)
    m0 = fmaxf(m0, __shfl_xor_sync(0xffffffffu, m0, 1));
    m0 = fmaxf(m0, __shfl_xor_sync(0xffffffffu, m0, 2));
    m1 = fmaxf(m1, __shfl_xor_sync(0xffffffffu, m1, 1));
    m1 = fmaxf(m1, __shfl_xor_sync(0xffffffffu, m1, 2));
    if (cfr == 0) {
        red[(row0g + 0) * 5 + wg] = m0;
        red[(row0g + 8) * 5 + wg] = m1;
    }
    __syncthreads();
    {
        const float* q0 = red + (row0g + 0) * 5;
        const float* q1 = red + (row0g + 8) * 5;
        m0 = fmaxf(fmaxf(q0[0], q0[1]), fmaxf(q0[2], q0[3]));
        m1 = fmaxf(fmaxf(q1[0], q1[1]), fmaxf(q1[2], q1[3]));
    }
    __syncthreads();   // all reads of red done before sum overwrites

    // exp + store P (unnormalized) + row-sum partials. P reuses K region.
    float* Ps = Ks;
    float s0 = 0.f, s1 = 0.f;
    float* P0 = Ps + (row0g + 0) * APS + wg * 40 + 2 * cfr;
    float* P1 = Ps + (row0g + 8) * APS + wg * 40 + 2 * cfr;
#pragma unroll
    for (int nt = 0; nt < 5; ++nt) {
        float e0 = __expf(acc[nt][0] - m0);
        float e1 = __expf(acc[nt][1] - m0);
        s0 += e0 + e1;
        *(float2*)(P0 + nt * 8) = make_float2(e0, e1);
        float e2 = __expf(acc[nt][2] - m1);
        float e3 = __expf(acc[nt][3] - m1);
        s1 += e2 + e3;
        *(float2*)(P1 + nt * 8) = make_float2(e2, e3);
    }
    s0 += __shfl_xor_sync(0xffffffffu, s0, 1);
    s0 += __shfl_xor_sync(0xffffffffu, s0, 2);
    s1 += __shfl_xor_sync(0xffffffffu, s1, 1);
    s1 += __shfl_xor_sync(0xffffffffu, s1, 2);
    if (cfr == 0) {
        red[(row0g + 0) * 5 + wg] = s0;
        red[(row0g + 8) * 5 + wg] = s1;
    }
    __syncthreads();
    if (tid < AR) {
        const float* q = red + tid * 5;
        rinv[tid] = 1.0f / (q[0] + q[1] + q[2] + q[3]);
    }
    __syncthreads();

    // ---- phase 3: out = P @ V  (2 rows x 4 dh per thread; R10 verified) ----
    const int dhg  = tid & 15;
    const int rowg = tid >> 4;
    const int pcol = dhg * 4;
    const int r0p  = rowg * 2;

    float pv0[4] = {0.f, 0.f, 0.f, 0.f};
    float pv1[4] = {0.f, 0.f, 0.f, 0.f};

    const float* Pr0 = Ps + (r0p + 0) * APS;
    const float* Pr1 = Ps + (r0p + 1) * APS;
    const float* Vp  = Vs + pcol;

#pragma unroll 2
    for (int k = 0; k < AU; k += 2) {
        float2 p0 = *(const float2*)(Pr0 + k);
        float2 p1 = *(const float2*)(Pr1 + k);
        float4 v0 = *(const float4*)(Vp + (k + 0) * AVS);
        float4 v1 = *(const float4*)(Vp + (k + 1) * AVS);
        pv0[0] += p0.x * v0.x + p0.y * v1.x;
        pv0[1] += p0.x * v0.y + p0.y * v1.y;
        pv0[2] += p0.x * v0.z + p0.y * v1.z;
        pv0[3] += p0.x * v0.w + p0.y * v1.w;
        pv1[0] += p1.x * v0.x + p1.y * v1.x;
        pv1[1] += p1.x * v0.y + p1.y * v1.y;
        pv1[2] += p1.x * v0.z + p1.y * v1.z;
        pv1[3] += p1.x * v0.w + p1.y * v1.w;
    }

    const float i0 = rinv[r0p + 0];
    const float i1 = rinv[r0p + 1];
    float* o0 = g_attn + base + (size_t)(t0 + r0p + 0) * DD + pcol;
    float* o1 = g_attn + base + (size_t)(t0 + r0p + 1) * DD + pcol;
    *(float4*)o0 = make_float4(pv0[0] * i0, pv0[1] * i0, pv0[2] * i0, pv0[3] * i0);
    *(float4*)o1 = make_float4(pv1[0] * i1, pv1[1] * i1, pv1[2] * i1, pv1[3] * i1);
}

// ---------------- launch ----------------
extern "C" void kernel_launch(void* const* d_in, const int* in_sizes, int n_in,
                              void* d_out, int out_size)
{
    const float* x  = (const float*)d_in[0];
    const float* wq = (const float*)d_in[1];
    const float* bq = (const float*)d_in[2];
    const float* wk = (const float*)d_in[3];
    const float* bk = (const float*)d_in[4];
    const float* wv = (const float*)d_in[5];
    const float* bv = (const float*)d_in[6];
    const float* wo = (const float*)d_in[7];
    const float* bo = (const float*)d_in[8];

    cudaFuncSetAttribute(gemm_qkv_tc,
                         cudaFuncAttributeMaxDynamicSharedMemorySize, SMEM_BYTES);
    cudaFuncSetAttribute(gemm_out_tc,
                         cudaFuncAttributeMaxDynamicSharedMemorySize, SMEM_BYTES);
    cudaFuncSetAttribute(attn_tile_kernel,
                         cudaFuncAttributeMaxDynamicSharedMemorySize, ATT_SMEM_BYTES);

    dim3 gq(GN / BN, GM / BM, 3);
    gemm_qkv_tc<<<gq, 256, SMEM_BYTES>>>(x, wq, bq, wk, bk, wv, bv);

    attn_tile_kernel<<<dim3(TT / AR, NB * HH), 256, ATT_SMEM_BYTES>>>();

    dim3 go(GN / BN, GM / BM);
    gemm_out_tc<<<go, 256, SMEM_BYTES>>>(wo, bo, (float*)d_out);
}

// round 13
// speedup vs baseline: 1.2564x; 1.1015x over previous
#include <cuda_runtime.h>
#include <math.h>
#include <stdint.h>

// Problem constants
#define NB   2
#define TT   1024
#define DD   1024
#define HH   16
#define DHH  64
#define WW   64
#define WIN  129

// GEMM dims
#define GM 2048
#define GN 1024
#define GK 1024
// Tiling (R10 verified: 110.8us QKV)
#define BM 128
#define BN 128
#define BK 32
#define SROW 36
#define NITER (GK / BK)
#define SMEM_FLOATS (2 * 2 * BM * SROW)
#define SMEM_BYTES  (SMEM_FLOATS * 4)        // 73728

// Attention tiling: CTA = 32 t-rows, window union 160
#define AR   32
#define AU   160
#define AQS  68                  // frag banks 4*r4+cfr -> conflict-free
#define AKS  68
#define APS  164                 // 164 mod 32 = 4 -> conflict-free frags
#define AVTS 164
#define SM_Q   0                 // Q[32][68]   = 2176
#define SM_K   2176              // K[160][68]  = 10880 (reused as P[32][164])
#define SM_VT  13056             // Vt[64][164] = 10496 (V transposed)
#define SM_RED 23552             // red[32][5]  = 160
#define SM_INV 23712             // rinv[32]
#define ATT_SMEM_BYTES (23744 * 4)   // 94976 -> 2 CTAs/SM

// Scratch (device globals: allocation-free per harness rules)
__device__ float g_q[NB * TT * DD];
__device__ float g_k[NB * TT * DD];
__device__ float g_v[NB * TT * DD];
__device__ float g_attn[NB * TT * DD];

__device__ __forceinline__ float to_tf32(float x) {
    float r;
    asm("cvt.rna.tf32.f32 %0, %1;" : "=f"(r) : "f"(x));
    return r;
}

__device__ __forceinline__ void mma_16x8x8_tf32(float* d, const uint32_t* a,
                                                const uint32_t* b) {
    asm volatile(
        "mma.sync.aligned.m16n8k8.row.col.f32.tf32.tf32.f32 "
        "{%0,%1,%2,%3}, {%4,%5,%6,%7}, {%8,%9}, {%0,%1,%2,%3};"
        : "+f"(d[0]), "+f"(d[1]), "+f"(d[2]), "+f"(d[3])
        : "r"(a[0]), "r"(a[1]), "r"(a[2]), "r"(a[3]),
          "r"(b[0]), "r"(b[1]));
}

// ---------------------------------------------------------------------------
// tf32 mma.sync GEMM (R10 verbatim; measured 110.8us on QKV)
// ---------------------------------------------------------------------------
__device__ __forceinline__ void gemm_tc_body(
    const float* __restrict__ A, const float* __restrict__ B,
    const float* __restrict__ bias, float* __restrict__ C)
{
    extern __shared__ float smem[];
    float* Asm = smem;
    float* Bsm = smem + 2 * BM * SROW;

    const int tid  = threadIdx.x;
    const int lane = tid & 31;
    const int wid  = tid >> 5;
    const int wm   = wid >> 2;
    const int wn   = wid & 3;
    const int row0 = blockIdx.y * BM;
    const int col0 = blockIdx.x * BN;

    const int lrow = tid >> 3;
    const int lq   = tid & 7;

    float acc[4][4][4];
#pragma unroll
    for (int m = 0; m < 4; ++m)
#pragma unroll
        for (int n = 0; n < 4; ++n)
#pragma unroll
            for (int e = 0; e < 4; ++e) acc[m][n][e] = 0.f;

    float4 pa[4], pb[4];

#pragma unroll
    for (int p = 0; p < 4; ++p) {
        int r = p * 32 + lrow;
        pa[p] = *(const float4*)(A + (size_t)(row0 + r) * GK + lq * 4);
        pb[p] = *(const float4*)(B + (size_t)(col0 + r) * GK + lq * 4);
    }
#pragma unroll
    for (int p = 0; p < 4; ++p) {
        int r = p * 32 + lrow;
        float4 va = pa[p], vb = pb[p];
        va.x = to_tf32(va.x); va.y = to_tf32(va.y);
        va.z = to_tf32(va.z); va.w = to_tf32(va.w);
        vb.x = to_tf32(vb.x); vb.y = to_tf32(vb.y);
        vb.z = to_tf32(vb.z); vb.w = to_tf32(vb.w);
        *(float4*)(Asm + r * SROW + lq * 4) = va;
        *(float4*)(Bsm + r * SROW + lq * 4) = vb;
    }
    __syncthreads();

    const int c  = lane & 3;
    const int r4 = lane >> 2;

    for (int i = 0; i < NITER; ++i) {
        const int buf = i & 1;
        const float* Ab = Asm + buf * (BM * SROW);
        const float* Bb = Bsm + buf * (BM * SROW);

        if (i + 1 < NITER) {
            const int k0 = (i + 1) * BK;
#pragma unroll
            for (int p = 0; p < 4; ++p) {
                int r = p * 32 + lrow;
                pa[p] = *(const float4*)(A + (size_t)(row0 + r) * GK + k0 + lq * 4);
                pb[p] = *(const float4*)(B + (size_t)(col0 + r) * GK + k0 + lq * 4);
            }
        }

        const uint32_t* Au = (const uint32_t*)(Ab + (wm * 64 + r4) * SROW + c);
        const uint32_t* Bu = (const uint32_t*)(Bb + (wn * 32 + r4) * SROW + c);

#pragma unroll
        for (int kk = 0; kk < 4; ++kk) {
            uint32_t af[4][4], bf[4][2];
            const int ko = kk * 8;
#pragma unroll
            for (int m = 0; m < 4; ++m) {
                af[m][0] = Au[(m * 16 + 0) * SROW + ko + 0];
                af[m][1] = Au[(m * 16 + 8) * SROW + ko + 0];
                af[m][2] = Au[(m * 16 + 0) * SROW + ko + 4];
                af[m][3] = Au[(m * 16 + 8) * SROW + ko + 4];
            }
#pragma unroll
            for (int n = 0; n < 4; ++n) {
                bf[n][0] = Bu[n * 8 * SROW + ko + 0];
                bf[n][1] = Bu[n * 8 * SROW + ko + 4];
            }
#pragma unroll
            for (int m = 0; m < 4; ++m)
#pragma unroll
                for (int n = 0; n < 4; ++n)
                    mma_16x8x8_tf32(acc[m][n], af[m], bf[n]);
        }

        if (i + 1 < NITER) {
            float* Aw = Asm + (buf ^ 1) * (BM * SROW);
            float* Bw = Bsm + (buf ^ 1) * (BM * SROW);
#pragma unroll
            for (int p = 0; p < 4; ++p) {
                int r = p * 32 + lrow;
                float4 va = pa[p], vb = pb[p];
                va.x = to_tf32(va.x); va.y = to_tf32(va.y);
                va.z = to_tf32(va.z); va.w = to_tf32(va.w);
                vb.x = to_tf32(vb.x); vb.y = to_tf32(vb.y);
                vb.z = to_tf32(vb.z); vb.w = to_tf32(vb.w);
                *(float4*)(Aw + r * SROW + lq * 4) = va;
                *(float4*)(Bw + r * SROW + lq * 4) = vb;
            }
            __syncthreads();
        }
    }

#pragma unroll
    for (int m = 0; m < 4; ++m) {
#pragma unroll
        for (int h = 0; h < 2; ++h) {
            const int grow = row0 + wm * 64 + m * 16 + r4 + 8 * h;
            float* crow = C + (size_t)grow * GN;
#pragma unroll
            for (int n = 0; n < 4; ++n) {
                const int gcol = col0 + wn * 32 + n * 8 + 2 * c;
                float2 o;
                o.x = acc[m][n][2 * h + 0] + __ldg(&bias[gcol + 0]);
                o.y = acc[m][n][2 * h + 1] + __ldg(&bias[gcol + 1]);
                *(float2*)(crow + gcol) = o;
            }
        }
    }
}

__global__ __launch_bounds__(256, 2) void gemm_qkv_tc(
    const float* __restrict__ x,
    const float* __restrict__ wq, const float* __restrict__ bq,
    const float* __restrict__ wk, const float* __restrict__ bk,
    const float* __restrict__ wv, const float* __restrict__ bv)
{
    const float* B; const float* bias; float* C;
    if (blockIdx.z == 0)      { B = wq; bias = bq; C = g_q; }
    else if (blockIdx.z == 1) { B = wk; bias = bk; C = g_k; }
    else                      { B = wv; bias = bv; C = g_v; }
    gemm_tc_body(x, B, bias, C);
}

__global__ __launch_bounds__(256, 2) void gemm_out_tc(
    const float* __restrict__ wo, const float* __restrict__ bo,
    float* __restrict__ out)
{
    gemm_tc_body(g_attn, wo, bo, out);
}

// ---------------------------------------------------------------------------
// Tiled windowed attention, fully tensor-core. CTA = 32 t-rows; union 160.
// Phase 1: S = Q@K^T (tf32 MMA, warps 2M x 4colgroup)
// Phase 2: mask + softmax; P rounded to tf32 BEFORE sum and store (consistent)
// Phase 3: out = P@V via tf32 MMA with V stored TRANSPOSED (col-major B)
// ---------------------------------------------------------------------------
__global__ __launch_bounds__(256) void attn_tile_kernel()
{
    extern __shared__ float sm[];
    float* Qs   = sm + SM_Q;
    float* Ks   = sm + SM_K;      // reused as P[32][APS]
    float* Vt   = sm + SM_VT;     // V transposed [64][AVTS]
    float* red  = sm + SM_RED;    // [32][5]
    float* rinv = sm + SM_INV;    // [32]

    const int tid = threadIdx.x;
    const int t0  = blockIdx.x * AR;
    const int nh  = blockIdx.y;
    const int h   = nh & (HH - 1);
    const int n   = nh >> 4;
    const size_t base = (size_t)n * TT * DD + (size_t)h * DHH;

    // ---- loads: Q (scaled+tf32), K (tf32) row-major; V transposed (tf32) ----
    for (int idx = tid; idx < AR * 16; idx += 256) {
        int r = idx >> 4, cc = (idx & 15) << 2;
        float4 v = *(const float4*)(g_q + base + (size_t)(t0 + r) * DD + cc);
        v.x = to_tf32(v.x * 0.125f); v.y = to_tf32(v.y * 0.125f);
        v.z = to_tf32(v.z * 0.125f); v.w = to_tf32(v.w * 0.125f);
        *(float4*)(Qs + r * AQS + cc) = v;
    }
    for (int idx = tid; idx < AU * 16; idx += 256) {
        int r = idx >> 4, cc = (idx & 15) << 2;
        int pos = min(max(t0 - 64 + r, 0), TT - 1);
        float4 kv = *(const float4*)(g_k + base + (size_t)pos * DD + cc);
        kv.x = to_tf32(kv.x); kv.y = to_tf32(kv.y);
        kv.z = to_tf32(kv.z); kv.w = to_tf32(kv.w);
        *(float4*)(Ks + r * AKS + cc) = kv;
    }
    // V transpose: dh-major threads -> coalesced LDG.32, conflict-free STS.128
    {
        const int dh   = tid & 63;
        const int pgrp = tid >> 6;         // 0..3
        const float* vg = g_v + base + dh;
#pragma unroll
        for (int l = 0; l < 10; ++l) {
            int p0 = l * 16 + pgrp * 4;
            float4 vv;
            int q0 = min(max(t0 - 64 + p0 + 0, 0), TT - 1);
            int q1 = min(max(t0 - 64 + p0 + 1, 0), TT - 1);
            int q2 = min(max(t0 - 64 + p0 + 2, 0), TT - 1);
            int q3 = min(max(t0 - 64 + p0 + 3, 0), TT - 1);
            vv.x = to_tf32(vg[(size_t)q0 * DD]);
            vv.y = to_tf32(vg[(size_t)q1 * DD]);
            vv.z = to_tf32(vg[(size_t)q2 * DD]);
            vv.w = to_tf32(vg[(size_t)q3 * DD]);
            *(float4*)(Vt + dh * AVTS + p0) = vv;
        }
    }
    __syncthreads();

    const int lane = tid & 31, wid = tid >> 5;
    const int r4  = lane >> 2;
    const int cfr = lane & 3;
    const int mtile = wid & 1;          // rows mtile*16 + 0..15
    const int wg    = wid >> 1;         // cols wg*40 + 0..39 (5 n-tiles)

    // ---- phase 1: S = Q @ K^T via tf32 MMA ----
    float acc[5][4];
#pragma unroll
    for (int nt = 0; nt < 5; ++nt)
#pragma unroll
        for (int e = 0; e < 4; ++e) acc[nt][e] = 0.f;

    const uint32_t* Aq = (const uint32_t*)(Qs + (mtile * 16 + r4) * AQS + cfr);
    const uint32_t* Bk = (const uint32_t*)(Ks + (wg * 40 + r4) * AKS + cfr);
#pragma unroll
    for (int ks = 0; ks < 8; ++ks) {
        const int ko = ks * 8;
        uint32_t af[4];
        af[0] = Aq[ko];
        af[1] = Aq[8 * AQS + ko];
        af[2] = Aq[ko + 4];
        af[3] = Aq[8 * AQS + ko + 4];
#pragma unroll
        for (int nt = 0; nt < 5; ++nt) {
            uint32_t bf[2];
            bf[0] = Bk[nt * 8 * AKS + ko];
            bf[1] = Bk[nt * 8 * AKS + ko + 4];
            mma_16x8x8_tf32(acc[nt], af, bf);
        }
    }

    // ---- phase 2: mask + softmax in fragment domain ----
    const int lob = 64 - t0;
    const int hib = 1087 - t0;
    const int row0g = mtile * 16 + r4;
    const int lo0 = max(row0g, lob),     hi0 = min(row0g + 128, hib);
    const int lo1 = max(row0g + 8, lob), hi1 = min(row0g + 136, hib);

    float m0 = -1e30f, m1 = -1e30f;
#pragma unroll
    for (int nt = 0; nt < 5; ++nt) {
#pragma unroll
        for (int e = 0; e < 2; ++e) {
            int col = wg * 40 + nt * 8 + 2 * cfr + e;
            if (col < lo0 || col > hi0) acc[nt][e] = -1e30f;
            m0 = fmaxf(m0, acc[nt][e]);
            if (col < lo1 || col > hi1) acc[nt][2 + e] = -1e30f;
            m1 = fmaxf(m1, acc[nt][2 + e]);
        }
    }
    m0 = fmaxf(m0, __shfl_xor_sync(0xffffffffu, m0, 1));
    m0 = fmaxf(m0, __shfl_xor_sync(0xffffffffu, m0, 2));
    m1 = fmaxf(m1, __shfl_xor_sync(0xffffffffu, m1, 1));
    m1 = fmaxf(m1, __shfl_xor_sync(0xffffffffu, m1, 2));
    if (cfr == 0) {
        red[(row0g + 0) * 5 + wg] = m0;
        red[(row0g + 8) * 5 + wg] = m1;
    }
    __syncthreads();
    {
        const float* q0 = red + (row0g + 0) * 5;
        const float* q1 = red + (row0g + 8) * 5;
        m0 = fmaxf(fmaxf(q0[0], q0[1]), fmaxf(q0[2], q0[3]));
        m1 = fmaxf(fmaxf(q1[0], q1[1]), fmaxf(q1[2], q1[3]));
    }
    __syncthreads();

    // exp -> tf32-round -> sum of ROUNDED values -> store P. P reuses K region.
    float* Ps = Ks;
    float s0 = 0.f, s1 = 0.f;
    float* P0 = Ps + (row0g + 0) * APS + wg * 40 + 2 * cfr;
    float* P1 = Ps + (row0g + 8) * APS + wg * 40 + 2 * cfr;
#pragma unroll
    for (int nt = 0; nt < 5; ++nt) {
        float e0 = to_tf32(__expf(acc[nt][0] - m0));
        float e1 = to_tf32(__expf(acc[nt][1] - m0));
        s0 += e0 + e1;
        *(float2*)(P0 + nt * 8) = make_float2(e0, e1);
        float e2 = to_tf32(__expf(acc[nt][2] - m1));
        float e3 = to_tf32(__expf(acc[nt][3] - m1));
        s1 += e2 + e3;
        *(float2*)(P1 + nt * 8) = make_float2(e2, e3);
    }
    s0 += __shfl_xor_sync(0xffffffffu, s0, 1);
    s0 += __shfl_xor_sync(0xffffffffu, s0, 2);
    s1 += __shfl_xor_sync(0xffffffffu, s1, 1);
    s1 += __shfl_xor_sync(0xffffffffu, s1, 2);
    if (cfr == 0) {
        red[(row0g + 0) * 5 + wg] = s0;
        red[(row0g + 8) * 5 + wg] = s1;
    }
    __syncthreads();
    if (tid < AR) {
        const float* q = red + tid * 5;
        rinv[tid] = 1.0f / (q[0] + q[1] + q[2] + q[3]);
    }
    __syncthreads();

    // ---- phase 3: out = P @ V via tf32 MMA (B = Vt, col-major) ----
    // warp -> mtile (rows mtile*16+0..15), nbase = (wid>>1)*16 (2 n-tiles)
    const int nbase = (wid >> 1) * 16;
    float pv[2][4];
#pragma unroll
    for (int nt = 0; nt < 2; ++nt)
#pragma unroll
        for (int e = 0; e < 4; ++e) pv[nt][e] = 0.f;

    const uint32_t* Pa  = (const uint32_t*)(Ps + (mtile * 16 + r4) * APS + cfr);
    const uint32_t* Vb0 = (const uint32_t*)(Vt + (nbase + 0 + r4) * AVTS + cfr);
    const uint32_t* Vb1 = (const uint32_t*)(Vt + (nbase + 8 + r4) * AVTS + cfr);
#pragma unroll
    for (int ks = 0; ks < 20; ++ks) {
        const int kc = ks * 8;
        uint32_t af[4];
        af[0] = Pa[kc];
        af[1] = Pa[8 * APS + kc];
        af[2] = Pa[kc + 4];
        af[3] = Pa[8 * APS + kc + 4];
        uint32_t b0[2] = { Vb0[kc], Vb0[kc + 4] };
        uint32_t b1[2] = { Vb1[kc], Vb1[kc + 4] };
        mma_16x8x8_tf32(pv[0], af, b0);
        mma_16x8x8_tf32(pv[1], af, b1);
    }

    const float i0 = rinv[row0g];
    const float i1 = rinv[row0g + 8];
    float* orow0 = g_attn + base + (size_t)(t0 + row0g + 0) * DD;
    float* orow1 = g_attn + base + (size_t)(t0 + row0g + 8) * DD;
#pragma unroll
    for (int nt = 0; nt < 2; ++nt) {
        const int col = nbase + nt * 8 + 2 * cfr;
        *(float2*)(orow0 + col) = make_float2(pv[nt][0] * i0, pv[nt][1] * i0);
        *(float2*)(orow1 + col) = make_float2(pv[nt][2] * i1, pv[nt][3] * i1);
    }
}

// ---------------- launch ----------------
extern "C" void kernel_launch(void* const* d_in, const int* in_sizes, int n_in,
                              void* d_out, int out_size)
{
    const float* x  = (const float*)d_in[0];
    const float* wq = (const float*)d_in[1];
    const float* bq = (const float*)d_in[2];
    const float* wk = (const float*)d_in[3];
    const float* bk = (const float*)d_in[4];
    const float* wv = (const float*)d_in[5];
    const float* bv = (const float*)d_in[6];
    const float* wo = (const float*)d_in[7];
    const float* bo = (const float*)d_in[8];

    cudaFuncSetAttribute(gemm_qkv_tc,
                         cudaFuncAttributeMaxDynamicSharedMemorySize, SMEM_BYTES);
    cudaFuncSetAttribute(gemm_out_tc,
                         cudaFuncAttributeMaxDynamicSharedMemorySize, SMEM_BYTES);
    cudaFuncSetAttribute(attn_tile_kernel,
                         cudaFuncAttributeMaxDynamicSharedMemorySize, ATT_SMEM_BYTES);

    dim3 gq(GN / BN, GM / BM, 3);
    gemm_qkv_tc<<<gq, 256, SMEM_BYTES>>>(x, wq, bq, wk, bk, wv, bv);

    attn_tile_kernel<<<dim3(TT / AR, NB * HH), 256, ATT_SMEM_BYTES>>>();

    dim3 go(GN / BN, GM / BM);
    gemm_out_tc<<<go, 256, SMEM_BYTES>>>(wo, bo, (float*)d_out);
}